// round 4
// baseline (speedup 1.0000x reference)
#include <cuda_runtime.h>
#include <cstdint>

#define BTOT 256
#define NTOK 196
#define HEADS 16
#define HD 32
#define CDIM 512

// scratch (device globals: allocation-free rule)
__device__ float g_k[BTOT*HEADS*NTOK*HD];
__device__ float g_v[BTOT*HEADS*NTOK*HD];
__device__ float g_o[BTOT*NTOK*CDIM];
__device__ float g_bias[HEADS*NTOK*NTOK];

__device__ __forceinline__ uint32_t cvt_tf32(float x){
    uint32_t r; asm("cvt.rna.tf32.f32 %0,%1;":"=r"(r):"f"(x)); return r;
}
__device__ __forceinline__ void split2(float x, uint32_t& hi, uint32_t& lo){
    hi = cvt_tf32(x);
    lo = cvt_tf32(x - __uint_as_float(hi));
}
__device__ __forceinline__ void mma8(float* c, const uint32_t* a, uint32_t b0, uint32_t b1){
    asm volatile("mma.sync.aligned.m16n8k8.row.col.f32.tf32.tf32.f32 "
        "{%0,%1,%2,%3},{%4,%5,%6,%7},{%8,%9},{%0,%1,%2,%3};"
        : "+f"(c[0]),"+f"(c[1]),"+f"(c[2]),"+f"(c[3])
        : "r"(a[0]),"r"(a[1]),"r"(a[2]),"r"(a[3]),"r"(b0),"r"(b1));
}
__device__ __forceinline__ void cpa16(float* s, const float* g){
    uint32_t a = (uint32_t)__cvta_generic_to_shared(s);
    asm volatile("cp.async.cg.shared.global [%0],[%1],16;"::"r"(a),"l"(g));
}

// ---------------- bias gather: g_bias[h][n][m] = table[rpi(n,m)][h] ----------------
__global__ void bias_gather_kernel(const float* __restrict__ table){
    for (int i = blockIdx.x*256 + threadIdx.x; i < HEADS*NTOK*NTOK;
         i += gridDim.x*256) {
        int m = i % NTOK;
        int t = i / NTOK;
        int n = t % NTOK;
        int h = t / NTOK;
        int t1 = n/49, r1 = n%49, h1 = r1/7, w1 = r1%7;
        int t2 = m/49, r2 = m%49, h2 = r2/7, w2 = r2%7;
        int idx = (t1-t2+3)*169 + (h1-h2+6)*13 + (w1-w2+6);
        g_bias[i] = table[idx*HEADS + h];
    }
}

// ---------------- GEMM: C[M x NT] = A[M,512] @ W[NT,512]^T + b ; M=50176 ----------------
// EPI 0: NT=1024, scatter into g_k/g_v.   EPI 1: NT=512, A = g_o, plain write to out.
template<int EPI>
__global__ void __launch_bounds__(256,2) gemm_kernel(
    const float* __restrict__ Ain, const float* __restrict__ W,
    const float* __restrict__ bias, float* __restrict__ out)
{
    __shared__ float As[2][128*20];
    __shared__ float Bs[2][64*20];
    const float* A = (EPI==1) ? (const float*)g_o : Ain;

    int tid = threadIdx.x, lane = tid&31, wid = tid>>5;
    int bm = blockIdx.x*128, bn = blockIdx.y*64;
    int wm = (wid&3)*32, wn = (wid>>2)*32;

    float c[2][4][4] = {};

    // async-copy index precompute
    int arow0 = tid>>2, akq0 = (tid&3)*4;            // A f4 #1: rows 0-63
    int arow1 = (tid+256)>>2, akq1 = akq0;           // A f4 #2: rows 64-127
    int brow = tid>>2, bkq = (tid&3)*4;              // B f4

    // prologue: stage 0
    {
        cpa16(&As[0][arow0*20+akq0], A + (size_t)(bm+arow0)*512 + akq0);
        cpa16(&As[0][arow1*20+akq1], A + (size_t)(bm+arow1)*512 + akq1);
        cpa16(&Bs[0][brow*20+bkq],   W + (size_t)(bn+brow)*512 + bkq);
        asm volatile("cp.async.commit_group;" ::: "memory");
    }

    for (int kb = 0; kb < 512; kb += 16) {
        asm volatile("cp.async.wait_group 0;" ::: "memory");
        __syncthreads();
        int s = (kb>>4)&1;
        if (kb + 16 < 512) {
            int s2 = s^1, k2 = kb+16;
            cpa16(&As[s2][arow0*20+akq0], A + (size_t)(bm+arow0)*512 + k2 + akq0);
            cpa16(&As[s2][arow1*20+akq1], A + (size_t)(bm+arow1)*512 + k2 + akq1);
            cpa16(&Bs[s2][brow*20+bkq],   W + (size_t)(bn+brow)*512 + k2 + bkq);
            asm volatile("cp.async.commit_group;" ::: "memory");
        }
        const float* as = As[s];
        const float* bs = Bs[s];
#pragma unroll
        for (int k0 = 0; k0 < 16; k0 += 8) {
            uint32_t ahi[2][4], alo[2][4], bb[4][2];
            int ka = k0 + (lane&3);
#pragma unroll
            for (int mt = 0; mt < 2; mt++) {
                int ra = wm + mt*16 + (lane>>2);
                split2(as[ra*20+ka],       ahi[mt][0], alo[mt][0]);
                split2(as[(ra+8)*20+ka],   ahi[mt][1], alo[mt][1]);
                split2(as[ra*20+ka+4],     ahi[mt][2], alo[mt][2]);
                split2(as[(ra+8)*20+ka+4], ahi[mt][3], alo[mt][3]);
            }
#pragma unroll
            for (int nt = 0; nt < 4; nt++) {
                int nb = wn + nt*8 + (lane>>2);
                bb[nt][0] = cvt_tf32(bs[nb*20+ka]);
                bb[nt][1] = cvt_tf32(bs[nb*20+ka+4]);
            }
#pragma unroll
            for (int mt = 0; mt < 2; mt++)
#pragma unroll
                for (int nt = 0; nt < 4; nt++) {
                    mma8(c[mt][nt], ahi[mt], bb[nt][0], bb[nt][1]);
                    mma8(c[mt][nt], alo[mt], bb[nt][0], bb[nt][1]);
                }
        }
    }

    // epilogue
#pragma unroll
    for (int mt = 0; mt < 2; mt++) {
        int rbase = bm + wm + mt*16 + (lane>>2);
#pragma unroll
        for (int half = 0; half < 2; half++) {
            int row = rbase + half*8;
            int b_ = row / 196;
            int n  = row % 196;
#pragma unroll
            for (int nt = 0; nt < 4; nt++) {
#pragma unroll
                for (int e = 0; e < 2; e++) {
                    int col = bn + wn + nt*8 + (lane&3)*2 + e;
                    float v = c[mt][nt][half*2+e] + bias[col];
                    if (EPI == 0) {
                        int kvsel = col >> 9;
                        int hh = (col>>5)&15, d = col&31;
                        float* dst = kvsel ? g_v : g_k;
                        dst[(((size_t)b_*16+hh)*196+n)*32+d] = v;
                    } else {
                        out[(size_t)row*512 + col] = v;
                    }
                }
            }
        }
    }
}

// ---------------- fused attention: one block per (b_, h) ----------------
// smem: Ks 200x36, Vs 200x36, Ps 8 warps x 16x204, Rs 8x16
__global__ void __launch_bounds__(256) attn_kernel(const float* __restrict__ qg){
    extern __shared__ float sm[];
    float* Ks = sm;                 // 7200
    float* Vs = sm + 7200;          // 7200
    float* Ps = sm + 14400;         // 26112
    float* Rs = sm + 14400 + 26112; // 128

    int h = blockIdx.x, b_ = blockIdx.y, b = b_ >> 6;
    int tid = threadIdx.x, lane = tid&31, wid = tid>>5;

    const float* kg = g_k + (((size_t)b_*16 + h)*196)*32;
    const float* vg = g_v + (((size_t)b_*16 + h)*196)*32;

    // load K,V (196x32), zero-pad rows to 200
    for (int i = tid; i < 1600; i += 256) {
        int r = i>>3, q = (i&7)*4;
        float4 zk = make_float4(0.f,0.f,0.f,0.f);
        float4 zv = make_float4(0.f,0.f,0.f,0.f);
        if (r < 196) {
            zk = *(const float4*)(kg + r*32 + q);
            zv = *(const float4*)(vg + r*32 + q);
        }
        *(float4*)(Ks + r*36 + q) = zk;
        *(float4*)(Vs + r*36 + q) = zv;
    }
    __syncthreads();

    const float* bptr  = g_bias + (size_t)h*NTOK*NTOK;
    const float* qbase = qg + (((size_t)b*16 + h)*196)*32;
    const float scale = 0.17677669529663687f; // 32^-0.5
    float* Pw = Ps + wid*16*204;

    for (int t = wid; t < 13; t += 8) {
        int m0 = t*16;
        int r0 = m0 + (lane>>2), r1 = r0 + 8;

        // Q fragments (scaled, split hi/lo)
        uint32_t qhi[4][4], qlo[4][4];
#pragma unroll
        for (int kt = 0; kt < 4; kt++) {
            int k = kt*8 + (lane&3);
            float x0 = (r0 < 196) ? qbase[r0*32+k]*scale   : 0.f;
            float x1 = (r1 < 196) ? qbase[r1*32+k]*scale   : 0.f;
            float x2 = (r0 < 196) ? qbase[r0*32+k+4]*scale : 0.f;
            float x3 = (r1 < 196) ? qbase[r1*32+k+4]*scale : 0.f;
            split2(x0, qhi[kt][0], qlo[kt][0]);
            split2(x1, qhi[kt][1], qlo[kt][1]);
            split2(x2, qhi[kt][2], qlo[kt][2]);
            split2(x3, qhi[kt][3], qlo[kt][3]);
        }

        // S = Q K^T + bias, stored to Pw
        for (int nt = 0; nt < 25; nt++) {
            int cc = nt*8 + (lane&3)*2;
            float bv0 = 0.f, bv1 = 0.f, bv2 = 0.f, bv3 = 0.f;
            bool cok0 = cc < 196, cok1 = (cc+1) < 196;
            if (cok0 && r0 < 196) bv0 = bptr[r0*196+cc];
            if (cok1 && r0 < 196) bv1 = bptr[r0*196+cc+1];
            if (cok0 && r1 < 196) bv2 = bptr[r1*196+cc];
            if (cok1 && r1 < 196) bv3 = bptr[r1*196+cc+1];

            float cfr[4] = {0.f,0.f,0.f,0.f};
#pragma unroll
            for (int kt = 0; kt < 4; kt++) {
                int k = kt*8 + (lane&3);
                int cb = nt*8 + (lane>>2);
                uint32_t b0 = cvt_tf32(Ks[cb*36+k]);
                uint32_t b1 = cvt_tf32(Ks[cb*36+k+4]);
                mma8(cfr, qhi[kt], b0, b1);
                mma8(cfr, qlo[kt], b0, b1);
            }
            int rr = lane>>2;
            Pw[rr*204+cc]       = cok0 ? cfr[0]+bv0 : -1e30f;
            Pw[rr*204+cc+1]     = cok1 ? cfr[1]+bv1 : -1e30f;
            Pw[(rr+8)*204+cc]   = cok0 ? cfr[2]+bv2 : -1e30f;
            Pw[(rr+8)*204+cc+1] = cok1 ? cfr[3]+bv3 : -1e30f;
        }
        __syncwarp();

        // softmax (2 threads per row, exact fp32); 1/sum saved to Rs
        {
            int rr = lane>>1, hf = lane&1;
            float* pr = Pw + rr*204 + hf*100;
            float mx = -1e30f;
            for (int j = 0; j < 100; j++) mx = fmaxf(mx, pr[j]);
            mx = fmaxf(mx, __shfl_xor_sync(0xffffffffu, mx, 1));
            float sum = 0.f;
            for (int j = 0; j < 100; j++) {
                float e = __expf(pr[j] - mx);
                pr[j] = e;
                sum += e;
            }
            sum += __shfl_xor_sync(0xffffffffu, sum, 1);
            if (hf == 0) Rs[wid*16+rr] = 1.f/sum;
        }
        __syncwarp();

        // O = P V (split-TF32 on P)
        float o[4][4] = {};
        for (int kt = 0; kt < 25; kt++) {
            int k = kt*8 + (lane&3);
            int g = lane>>2;
            uint32_t phi[4], plo[4];
            split2(Pw[g*204+k],       phi[0], plo[0]);
            split2(Pw[(g+8)*204+k],   phi[1], plo[1]);
            split2(Pw[g*204+k+4],     phi[2], plo[2]);
            split2(Pw[(g+8)*204+k+4], phi[3], plo[3]);
#pragma unroll
            for (int dt = 0; dt < 4; dt++) {
                int d = dt*8 + g;
                uint32_t b0 = cvt_tf32(Vs[k*36+d]);
                uint32_t b1 = cvt_tf32(Vs[(k+4)*36+d]);
                mma8(o[dt], phi, b0, b1);
                mma8(o[dt], plo, b0, b1);
            }
        }

        // epilogue: fold 1/rowsum, write to g_o (B_,N,C) at channel h*32+d
        float inv0 = Rs[wid*16 + (lane>>2)];
        float inv1 = Rs[wid*16 + (lane>>2) + 8];
        float* og = g_o + ((size_t)b_*196)*512 + h*32;
#pragma unroll
        for (int dt = 0; dt < 4; dt++) {
            int d = dt*8 + (lane&3)*2;
            if (r0 < 196) {
                og[(size_t)r0*512 + d]   = o[dt][0]*inv0;
                og[(size_t)r0*512 + d+1] = o[dt][1]*inv0;
            }
            if (r1 < 196) {
                og[(size_t)r1*512 + d]   = o[dt][2]*inv1;
                og[(size_t)r1*512 + d+1] = o[dt][3]*inv1;
            }
        }
    }
}

extern "C" void kernel_launch(void* const* d_in, const int* in_sizes, int n_in,
                              void* d_out, int out_size) {
    const float* x   = (const float*)d_in[0];
    const float* qg  = (const float*)d_in[1];
    const float* kvw = (const float*)d_in[2];
    const float* kvb = (const float*)d_in[3];
    const float* pw  = (const float*)d_in[4];
    const float* pb  = (const float*)d_in[5];
    const float* bt  = (const float*)d_in[6];
    float* out = (float*)d_out;

    bias_gather_kernel<<<2402, 256>>>(bt);
    gemm_kernel<0><<<dim3(392,16), 256>>>(x, kvw, kvb, nullptr);

    cudaFuncSetAttribute(attn_kernel, cudaFuncAttributeMaxDynamicSharedMemorySize, 162560);
    attn_kernel<<<dim3(16,256), 256, 162560>>>(qg);

    gemm_kernel<1><<<dim3(392,8), 256>>>(nullptr, pw, pb, out);
}

// round 7
// speedup vs baseline: 1.0868x; 1.0868x over previous
#include <cuda_runtime.h>
#include <cstdint>

#define BTOT 256
#define NTOK 196
#define HEADS 16
#define HD 32
#define CDIM 512
#define MROWS (BTOT*NTOK)          // 50176
#define AELEM (MROWS*CDIM)         // 25690112

// scratch (device globals: allocation-free rule)
__device__ uint32_t g_xhi[AELEM];      // x pre-split tf32 hi
__device__ uint32_t g_xlo[AELEM];      // x pre-split tf32 lo
__device__ uint32_t g_ahi[AELEM];      // attn out pre-split hi
__device__ uint32_t g_alo[AELEM];      // attn out pre-split lo
__device__ uint32_t g_k[AELEM];        // K, tf32-converted  (B_,H,N,hd)
__device__ uint32_t g_v[AELEM];        // V, tf32-converted
__device__ uint32_t g_wkv[2*CDIM*CDIM];  // kv_w tf32
__device__ uint32_t g_wpr[CDIM*CDIM];    // proj_w tf32
__device__ float    g_bias[HEADS*NTOK*NTOK];

__device__ __forceinline__ uint32_t cvt_tf32(float x){
    uint32_t r; asm("cvt.rna.tf32.f32 %0,%1;":"=r"(r):"f"(x)); return r;
}
__device__ __forceinline__ void split2(float x, uint32_t& hi, uint32_t& lo){
    hi = cvt_tf32(x);
    lo = cvt_tf32(x - __uint_as_float(hi));
}
__device__ __forceinline__ void mma8(float* c, const uint32_t* a, uint32_t b0, uint32_t b1){
    asm volatile("mma.sync.aligned.m16n8k8.row.col.f32.tf32.tf32.f32 "
        "{%0,%1,%2,%3},{%4,%5,%6,%7},{%8,%9},{%0,%1,%2,%3};"
        : "+f"(c[0]),"+f"(c[1]),"+f"(c[2]),"+f"(c[3])
        : "r"(a[0]),"r"(a[1]),"r"(a[2]),"r"(a[3]),"r"(b0),"r"(b1));
}
__device__ __forceinline__ void cpa16(void* s, const void* g){
    uint32_t a = (uint32_t)__cvta_generic_to_shared(s);
    asm volatile("cp.async.cg.shared.global [%0],[%1],16;"::"r"(a),"l"(g));
}

// ---------------- pre-split x into tf32 hi/lo planes ----------------
__global__ void split_x_kernel(const float4* __restrict__ x){
    const int n4 = AELEM/4;
    for (int i = blockIdx.x*blockDim.x + threadIdx.x; i < n4; i += gridDim.x*blockDim.x){
        float4 v = x[i];
        uint4 h, l;
        split2(v.x, h.x, l.x);
        split2(v.y, h.y, l.y);
        split2(v.z, h.z, l.z);
        split2(v.w, h.w, l.w);
        ((uint4*)g_xhi)[i] = h;
        ((uint4*)g_xlo)[i] = l;
    }
}

// ---------------- pre-convert weights to tf32 ----------------
__global__ void conv_w_kernel(const float* __restrict__ kvw, const float* __restrict__ prw){
    const int nk = 2*CDIM*CDIM, np = CDIM*CDIM;
    for (int i = blockIdx.x*blockDim.x + threadIdx.x; i < nk+np; i += gridDim.x*blockDim.x){
        if (i < nk) g_wkv[i] = cvt_tf32(kvw[i]);
        else        g_wpr[i-nk] = cvt_tf32(prw[i-nk]);
    }
}

// ---------------- bias gather: g_bias[h][n][m] = table[rpi(n,m)][h] ----------------
__global__ void bias_gather_kernel(const float* __restrict__ table){
    for (int i = blockIdx.x*256 + threadIdx.x; i < HEADS*NTOK*NTOK; i += gridDim.x*256) {
        int m = i % NTOK;
        int t = i / NTOK;
        int n = t % NTOK;
        int h = t / NTOK;
        int t1 = n/49, r1 = n%49, h1 = r1/7, w1 = r1%7;
        int t2 = m/49, r2 = m%49, h2 = r2/7, w2 = r2%7;
        int idx = (t1-t2+3)*169 + (h1-h2+6)*13 + (w1-w2+6);
        g_bias[i] = table[idx*HEADS + h];
    }
}

// ---------------- GEMM: C[M x NT] = A[M,512] @ W[NT,512]^T + b ----------------
// Operands pre-converted: A as (hi,lo) tf32 planes, W as tf32.
// EPI 0: NT=1024, A=x, scatter tf32 into g_k/g_v.  EPI 1: NT=512, A=attn out, float out.
// blockIdx.x = bn (fast) so a residency wave covers all N-tiles -> A read once from DRAM.
template<int EPI>
__global__ void __launch_bounds__(256,3) gemm_kernel(
    const float* __restrict__ bias, float* __restrict__ out)
{
    __shared__ uint32_t Ah[2][128*20];
    __shared__ uint32_t Al[2][128*20];
    __shared__ uint32_t Bs[2][64*20];
    const uint32_t* Ahi = (EPI==0) ? g_xhi : g_ahi;
    const uint32_t* Alo = (EPI==0) ? g_xlo : g_alo;
    const uint32_t* W   = (EPI==0) ? g_wkv : g_wpr;

    int tid = threadIdx.x, lane = tid&31, wid = tid>>5;
    int bn = blockIdx.x*64, bm = blockIdx.y*128;
    int wm = (wid&3)*32, wn = (wid>>2)*32;

    float c[2][4][4] = {};

    int arow0 = tid>>2, akq = (tid&3)*4;     // rows 0-63
    int arow1 = arow0 + 64;                  // rows 64-127
    int brow = tid>>2;

    // prologue: stage 0
    {
        cpa16(&Ah[0][arow0*20+akq], Ahi + (size_t)(bm+arow0)*512 + akq);
        cpa16(&Ah[0][arow1*20+akq], Ahi + (size_t)(bm+arow1)*512 + akq);
        cpa16(&Al[0][arow0*20+akq], Alo + (size_t)(bm+arow0)*512 + akq);
        cpa16(&Al[0][arow1*20+akq], Alo + (size_t)(bm+arow1)*512 + akq);
        cpa16(&Bs[0][brow*20+akq],  W   + (size_t)(bn+brow)*512 + akq);
        asm volatile("cp.async.commit_group;" ::: "memory");
    }

    for (int kb = 0; kb < 512; kb += 16) {
        asm volatile("cp.async.wait_group 0;" ::: "memory");
        __syncthreads();
        int s = (kb>>4)&1;
        if (kb + 16 < 512) {
            int s2 = s^1, k2 = kb+16;
            cpa16(&Ah[s2][arow0*20+akq], Ahi + (size_t)(bm+arow0)*512 + k2 + akq);
            cpa16(&Ah[s2][arow1*20+akq], Ahi + (size_t)(bm+arow1)*512 + k2 + akq);
            cpa16(&Al[s2][arow0*20+akq], Alo + (size_t)(bm+arow0)*512 + k2 + akq);
            cpa16(&Al[s2][arow1*20+akq], Alo + (size_t)(bm+arow1)*512 + k2 + akq);
            cpa16(&Bs[s2][brow*20+akq],  W   + (size_t)(bn+brow)*512 + k2 + akq);
            asm volatile("cp.async.commit_group;" ::: "memory");
        }
        const uint32_t* ah = Ah[s];
        const uint32_t* al = Al[s];
        const uint32_t* bs = Bs[s];
#pragma unroll
        for (int k0 = 0; k0 < 16; k0 += 8) {
            uint32_t ahi[2][4], alo[2][4], bb[4][2];
            int ka = k0 + (lane&3);
#pragma unroll
            for (int mt = 0; mt < 2; mt++) {
                int ra = wm + mt*16 + (lane>>2);
                ahi[mt][0] = ah[ra*20+ka];      alo[mt][0] = al[ra*20+ka];
                ahi[mt][1] = ah[(ra+8)*20+ka];  alo[mt][1] = al[(ra+8)*20+ka];
                ahi[mt][2] = ah[ra*20+ka+4];    alo[mt][2] = al[ra*20+ka+4];
                ahi[mt][3] = ah[(ra+8)*20+ka+4];alo[mt][3] = al[(ra+8)*20+ka+4];
            }
#pragma unroll
            for (int nt = 0; nt < 4; nt++) {
                int nb = wn + nt*8 + (lane>>2);
                bb[nt][0] = bs[nb*20+ka];
                bb[nt][1] = bs[nb*20+ka+4];
            }
#pragma unroll
            for (int mt = 0; mt < 2; mt++)
#pragma unroll
                for (int nt = 0; nt < 4; nt++) {
                    mma8(c[mt][nt], ahi[mt], bb[nt][0], bb[nt][1]);
                    mma8(c[mt][nt], alo[mt], bb[nt][0], bb[nt][1]);
                }
        }
    }

    // epilogue
#pragma unroll
    for (int mt = 0; mt < 2; mt++) {
        int rbase = bm + wm + mt*16 + (lane>>2);
#pragma unroll
        for (int half = 0; half < 2; half++) {
            int row = rbase + half*8;
            int b_ = row / 196;
            int n  = row % 196;
#pragma unroll
            for (int nt = 0; nt < 4; nt++) {
#pragma unroll
                for (int e = 0; e < 2; e++) {
                    int col = bn + wn + nt*8 + (lane&3)*2 + e;
                    float v = c[mt][nt][half*2+e] + bias[col];
                    if (EPI == 0) {
                        int kvsel = col >> 9;
                        int hh = (col>>5)&15, d = col&31;
                        uint32_t* dst = kvsel ? g_v : g_k;
                        dst[(((size_t)b_*16+hh)*196+n)*32+d] = cvt_tf32(v);
                    } else {
                        out[(size_t)row*512 + col] = v;
                    }
                }
            }
        }
    }
}

// ---------------- fused attention: one block per (b_, h), 13 warps = 1 tile each ----
// smem (u32 words): Ks 200x36, Vs 200x36, Ps 13 x 16x204 (float), Rs 13x16 (float)
__global__ void __launch_bounds__(416,1) attn_kernel(const float* __restrict__ qg){
    extern __shared__ uint32_t smu[];
    uint32_t* Ks = smu;                       // 7200 words
    uint32_t* Vs = smu + 7200;                // 7200 words
    float* Ps = (float*)(smu + 14400);        // 13*16*204 = 42432
    float* Rs = Ps + 42432;                   // 208

    int h = blockIdx.x, b_ = blockIdx.y, b = b_ >> 6;
    int tid = threadIdx.x, lane = tid&31, wid = tid>>5;

    const uint4* kg = (const uint4*)(g_k + (((size_t)b_*16 + h)*196)*32);
    const uint4* vg = (const uint4*)(g_v + (((size_t)b_*16 + h)*196)*32);

    // load K,V (196x32 tf32-u32), zero-pad rows to 200
    for (int i = tid; i < 1600; i += 416) {
        int r = i>>3, q = (i&7)*4;
        uint4 zk = make_uint4(0,0,0,0);
        uint4 zv = make_uint4(0,0,0,0);
        if (r < 196) {
            zk = kg[r*8 + (i&7)];
            zv = vg[r*8 + (i&7)];
        }
        *(uint4*)(Ks + r*36 + q) = zk;
        *(uint4*)(Vs + r*36 + q) = zv;
    }
    __syncthreads();

    const float* bptr  = g_bias + (size_t)h*NTOK*NTOK;
    const float* qbase = qg + (((size_t)b*16 + h)*196)*32;
    const float scale = 0.17677669529663687f; // 32^-0.5
    float* Pw = Ps + wid*16*204;

    {
        int t = wid;                        // 0..12, one 16-row tile per warp
        int r0 = t*16 + (lane>>2), r1 = r0 + 8;

        // Q fragments (scaled, split hi/lo)
        uint32_t qhi[4][4], qlo[4][4];
#pragma unroll
        for (int kt = 0; kt < 4; kt++) {
            int k = kt*8 + (lane&3);
            float x0 = (r0 < 196) ? qbase[r0*32+k]*scale   : 0.f;
            float x1 = (r1 < 196) ? qbase[r1*32+k]*scale   : 0.f;
            float x2 = (r0 < 196) ? qbase[r0*32+k+4]*scale : 0.f;
            float x3 = (r1 < 196) ? qbase[r1*32+k+4]*scale : 0.f;
            split2(x0, qhi[kt][0], qlo[kt][0]);
            split2(x1, qhi[kt][1], qlo[kt][1]);
            split2(x2, qhi[kt][2], qlo[kt][2]);
            split2(x3, qhi[kt][3], qlo[kt][3]);
        }

        // S = Q K^T + bias -> Pw
        for (int nt = 0; nt < 25; nt++) {
            int cc = nt*8 + (lane&3)*2;
            float bv0 = 0.f, bv1 = 0.f, bv2 = 0.f, bv3 = 0.f;
            bool cok0 = cc < 196, cok1 = (cc+1) < 196;
            if (cok0 && r0 < 196) bv0 = bptr[r0*196+cc];
            if (cok1 && r0 < 196) bv1 = bptr[r0*196+cc+1];
            if (cok0 && r1 < 196) bv2 = bptr[r1*196+cc];
            if (cok1 && r1 < 196) bv3 = bptr[r1*196+cc+1];

            float cfr[4] = {0.f,0.f,0.f,0.f};
#pragma unroll
            for (int kt = 0; kt < 4; kt++) {
                int k = kt*8 + (lane&3);
                int cb = nt*8 + (lane>>2);
                uint32_t b0 = Ks[cb*36+k];
                uint32_t b1 = Ks[cb*36+k+4];
                mma8(cfr, qhi[kt], b0, b1);
                mma8(cfr, qlo[kt], b0, b1);
            }
            int rr = lane>>2;
            Pw[rr*204+cc]       = cok0 ? cfr[0]+bv0 : -1e30f;
            Pw[rr*204+cc+1]     = cok1 ? cfr[1]+bv1 : -1e30f;
            Pw[(rr+8)*204+cc]   = cok0 ? cfr[2]+bv2 : -1e30f;
            Pw[(rr+8)*204+cc+1] = cok1 ? cfr[3]+bv3 : -1e30f;
        }
        __syncwarp();

        // softmax (2 threads per row, exact fp32); 1/sum saved to Rs
        {
            int rr = lane>>1, hf = lane&1;
            float* pr = Pw + rr*204 + hf*100;
            float mx = -1e30f;
            for (int j = 0; j < 100; j++) mx = fmaxf(mx, pr[j]);
            mx = fmaxf(mx, __shfl_xor_sync(0xffffffffu, mx, 1));
            float sum = 0.f;
            for (int j = 0; j < 100; j++) {
                float e = __expf(pr[j] - mx);
                pr[j] = e;
                sum += e;
            }
            sum += __shfl_xor_sync(0xffffffffu, sum, 1);
            if (hf == 0) Rs[wid*16+rr] = 1.f/sum;
        }
        __syncwarp();

        // O = P V (split-TF32 on P)
        float o[4][4] = {};
        for (int kt = 0; kt < 25; kt++) {
            int k = kt*8 + (lane&3);
            int g = lane>>2;
            uint32_t phi[4], plo[4];
            split2(Pw[g*204+k],       phi[0], plo[0]);
            split2(Pw[(g+8)*204+k],   phi[1], plo[1]);
            split2(Pw[g*204+k+4],     phi[2], plo[2]);
            split2(Pw[(g+8)*204+k+4], phi[3], plo[3]);
#pragma unroll
            for (int dt = 0; dt < 4; dt++) {
                int d = dt*8 + g;
                uint32_t b0 = Vs[k*36+d];
                uint32_t b1 = Vs[(k+4)*36+d];
                mma8(o[dt], phi, b0, b1);
                mma8(o[dt], plo, b0, b1);
            }
        }

        // epilogue: fold 1/rowsum, write PRE-SPLIT output at channel h*32+d
        float inv0 = Rs[wid*16 + (lane>>2)];
        float inv1 = Rs[wid*16 + (lane>>2) + 8];
        size_t obase = (size_t)b_*196*512 + h*32;
#pragma unroll
        for (int dt = 0; dt < 4; dt++) {
            int d = dt*8 + (lane&3)*2;
#pragma unroll
            for (int e = 0; e < 2; e++) {
                if (r0 < 196) {
                    uint32_t hh, ll;
                    split2(o[dt][e]*inv0, hh, ll);
                    g_ahi[obase + (size_t)r0*512 + d + e] = hh;
                    g_alo[obase + (size_t)r0*512 + d + e] = ll;
                }
                if (r1 < 196) {
                    uint32_t hh, ll;
                    split2(o[dt][2+e]*inv1, hh, ll);
                    g_ahi[obase + (size_t)r1*512 + d + e] = hh;
                    g_alo[obase + (size_t)r1*512 + d + e] = ll;
                }
            }
        }
    }
}

extern "C" void kernel_launch(void* const* d_in, const int* in_sizes, int n_in,
                              void* d_out, int out_size) {
    const float* x   = (const float*)d_in[0];
    const float* qg  = (const float*)d_in[1];
    const float* kvw = (const float*)d_in[2];
    const float* kvb = (const float*)d_in[3];
    const float* pw  = (const float*)d_in[4];
    const float* pb  = (const float*)d_in[5];
    const float* bt  = (const float*)d_in[6];
    float* out = (float*)d_out;

    split_x_kernel<<<8192, 512>>>((const float4*)x);
    conv_w_kernel<<<1536, 512>>>(kvw, pw);
    bias_gather_kernel<<<2402, 256>>>(bt);

    gemm_kernel<0><<<dim3(16,392), 256>>>(kvb, nullptr);

    cudaFuncSetAttribute(attn_kernel, cudaFuncAttributeMaxDynamicSharedMemorySize, 228160);
    attn_kernel<<<dim3(16,256), 416, 228160>>>(qg);

    gemm_kernel<1><<<dim3(8,392), 256>>>(pb, out);
}

// round 10
// speedup vs baseline: 1.4669x; 1.3498x over previous
#include <cuda_runtime.h>
#include <cuda_bf16.h>
#include <cstdint>

#define BTOT 256
#define NTOK 196
#define HEADS 16
#define HD 32
#define CDIM 512
#define MROWS (BTOT*NTOK)          // 50176
#define AELEM (MROWS*CDIM)         // 25690112

// ---------------- scratch (device globals) ----------------
// bf16 hi/lo planes, plain row-major [rows][512]
__device__ __align__(16) uint16_t g_xhi[AELEM];
__device__ __align__(16) uint16_t g_xlo[AELEM];
__device__ __align__(16) uint16_t g_ahi[AELEM];
__device__ __align__(16) uint16_t g_alo[AELEM];
__device__ __align__(16) uint16_t g_wkvh[2*CDIM*CDIM];
__device__ __align__(16) uint16_t g_wkvl[2*CDIM*CDIM];
__device__ __align__(16) uint16_t g_wprh[CDIM*CDIM];
__device__ __align__(16) uint16_t g_wprl[CDIM*CDIM];
// K,V tf32-converted for the attention kernel (B_,H,N,hd)
__device__ __align__(16) uint32_t g_k[AELEM];
__device__ __align__(16) uint32_t g_v[AELEM];
__device__ float g_bias[HEADS*NTOK*NTOK];

// ---------------- helpers ----------------
__device__ __forceinline__ uint32_t cvt_tf32(float x){
    uint32_t r; asm("cvt.rna.tf32.f32 %0,%1;":"=r"(r):"f"(x)); return r;
}
__device__ __forceinline__ void split2(float x, uint32_t& hi, uint32_t& lo){
    hi = cvt_tf32(x);
    lo = cvt_tf32(x - __uint_as_float(hi));
}
__device__ __forceinline__ void bsplit(float x, uint16_t& hi, uint16_t& lo){
    __nv_bfloat16 h = __float2bfloat16(x);
    __nv_bfloat16 l = __float2bfloat16(x - __bfloat162float(h));
    hi = __bfloat16_as_ushort(h);
    lo = __bfloat16_as_ushort(l);
}
// legacy tf32 mma (attention)
__device__ __forceinline__ void mma8(float* c, const uint32_t* a, uint32_t b0, uint32_t b1){
    asm volatile("mma.sync.aligned.m16n8k8.row.col.f32.tf32.tf32.f32 "
        "{%0,%1,%2,%3},{%4,%5,%6,%7},{%8,%9},{%0,%1,%2,%3};"
        : "+f"(c[0]),"+f"(c[1]),"+f"(c[2]),"+f"(c[3])
        : "r"(a[0]),"r"(a[1]),"r"(a[2]),"r"(a[3]),"r"(b0),"r"(b1));
}
// bf16 mma m16n8k16 (GEMMs)
__device__ __forceinline__ void mma16(float* c, const uint32_t* a, uint32_t b0, uint32_t b1){
    asm volatile("mma.sync.aligned.m16n8k16.row.col.f32.bf16.bf16.f32 "
        "{%0,%1,%2,%3},{%4,%5,%6,%7},{%8,%9},{%0,%1,%2,%3};"
        : "+f"(c[0]),"+f"(c[1]),"+f"(c[2]),"+f"(c[3])
        : "r"(a[0]),"r"(a[1]),"r"(a[2]),"r"(a[3]),"r"(b0),"r"(b1));
}
__device__ __forceinline__ void cpa16(void* s, const void* g){
    uint32_t a = (uint32_t)__cvta_generic_to_shared(s);
    asm volatile("cp.async.cg.shared.global [%0],[%1],16;"::"r"(a),"l"(g));
}

// ---------------- pre-split x into bf16 hi/lo planes ----------------
__global__ void split_x_kernel(const float* __restrict__ x){
    const int ng = MROWS*64;  // 8-elem granules
    for (int i = blockIdx.x*blockDim.x + threadIdx.x; i < ng; i += gridDim.x*blockDim.x){
        int row = i>>6, k0 = (i&63)*8;
        const float* src = x + (size_t)row*512 + k0;
        uint16_t h[8], l[8];
#pragma unroll
        for (int j = 0; j < 8; j++) bsplit(src[j], h[j], l[j]);
        size_t e = (size_t)row*512 + k0;
        *(uint4*)(g_xhi + e) = *(uint4*)h;
        *(uint4*)(g_xlo + e) = *(uint4*)l;
    }
}

// ---------------- pre-split weights ----------------
__global__ void conv_w_kernel(const float* __restrict__ kvw, const float* __restrict__ prw){
    const int nk = 2*CDIM*64, np = CDIM*64; // granules
    for (int i = blockIdx.x*blockDim.x + threadIdx.x; i < nk+np; i += gridDim.x*blockDim.x){
        const float* W; uint16_t *Ph, *Pl; int gi;
        if (i < nk) { W = kvw; Ph = g_wkvh; Pl = g_wkvl; gi = i; }
        else        { W = prw; Ph = g_wprh; Pl = g_wprl; gi = i-nk; }
        int row = gi>>6, k0 = (gi&63)*8;
        const float* src = W + (size_t)row*512 + k0;
        uint16_t h[8], l[8];
#pragma unroll
        for (int j = 0; j < 8; j++) bsplit(src[j], h[j], l[j]);
        size_t e = (size_t)row*512 + k0;
        *(uint4*)(Ph + e) = *(uint4*)h;
        *(uint4*)(Pl + e) = *(uint4*)l;
    }
}

// ---------------- bias gather ----------------
__global__ void bias_gather_kernel(const float* __restrict__ table){
    for (int i = blockIdx.x*256 + threadIdx.x; i < HEADS*NTOK*NTOK; i += gridDim.x*256) {
        int m = i % NTOK;
        int t = i / NTOK;
        int n = t % NTOK;
        int h = t / NTOK;
        int t1 = n/49, r1 = n%49, h1 = r1/7, w1 = r1%7;
        int t2 = m/49, r2 = m%49, h2 = r2/7, w2 = r2%7;
        int idx = (t1-t2+3)*169 + (h1-h2+6)*13 + (w1-w2+6);
        g_bias[i] = table[idx*HEADS + h];
    }
}

// ---------------- bf16 3-term GEMM: C[M x NT] = A @ W^T + b ----------------
// 128x128 CTA tile, BK=32 (16 u32 pairs), double-buffered cp.async.
// smem u32 layout per stage (stride 2560 u32 per plane): Ah, Al, Bh, Bl
// EPI 0: NT=1024, scatter tf32 -> g_k/g_v.  EPI 1: NT=512, float -> out.
template<int EPI>
__global__ void __launch_bounds__(256,2) gemm_kernel(
    const float* __restrict__ bias, float* __restrict__ out)
{
    extern __shared__ uint32_t smg[];   // 2 stages * 4 planes * 128*20 u32 = 81920 B

    const uint16_t* Ahi = (EPI==0) ? g_xhi  : g_ahi;
    const uint16_t* Alo = (EPI==0) ? g_xlo  : g_alo;
    const uint16_t* Bhi = (EPI==0) ? g_wkvh : g_wprh;
    const uint16_t* Blo = (EPI==0) ? g_wkvl : g_wprl;

    int tid = threadIdx.x, lane = tid&31, wid = tid>>5;
    int bn = blockIdx.x*128, bm = blockIdx.y*128;
    int wm = (wid&1)*64, wn = (wid>>1)*32;

    float c[4][4][4] = {};

    // cp.async indices: idx in [0,512): row=idx>>2, seg=idx&3 (16B = 8 bf16)
    int r0i = tid>>2, s0 = tid&3;
    int r1i = (tid+256)>>2, s1 = s0;

    auto fill = [&](int stage, int kb){
        uint32_t* base = smg + stage*10240;
        const uint16_t* srcs[4] = { Ahi, Alo, Bhi, Blo };
        size_t rb[4] = { (size_t)(bm+r0i), (size_t)(bm+r0i), (size_t)(bn+r0i), (size_t)(bn+r0i) };
        size_t rb2[4] = { (size_t)(bm+r1i), (size_t)(bm+r1i), (size_t)(bn+r1i), (size_t)(bn+r1i) };
#pragma unroll
        for (int p = 0; p < 4; p++) {
            uint32_t* dst = base + p*2560;
            cpa16(dst + r0i*20 + s0*4, srcs[p] + rb[p]*512  + kb + s0*8);
            cpa16(dst + r1i*20 + s1*4, srcs[p] + rb2[p]*512 + kb + s1*8);
        }
        asm volatile("cp.async.commit_group;" ::: "memory");
    };

    fill(0, 0);

    for (int kb = 0; kb < 512; kb += 32) {
        asm volatile("cp.async.wait_group 0;" ::: "memory");
        __syncthreads();
        int s = (kb>>5)&1;
        if (kb + 32 < 512) fill(s^1, kb+32);

        const uint32_t* Ahs = smg + s*10240;
        const uint32_t* Als = Ahs + 2560;
        const uint32_t* Bhs = Ahs + 5120;
        const uint32_t* Bls = Ahs + 7680;

        int c4 = lane&3, rg = lane>>2;
#pragma unroll
        for (int t = 0; t < 2; t++) {
            uint32_t bh[4][2], bl[4][2];
#pragma unroll
            for (int nt = 0; nt < 4; nt++) {
                int baseb = (wn + nt*8 + rg)*20 + t*8;
                bh[nt][0] = Bhs[baseb+c4];  bh[nt][1] = Bhs[baseb+c4+4];
                bl[nt][0] = Bls[baseb+c4];  bl[nt][1] = Bls[baseb+c4+4];
            }
#pragma unroll
            for (int mt = 0; mt < 4; mt++) {
                int basea = (wm + mt*16 + rg)*20 + t*8;
                uint32_t ah[4], al[4];
                ah[0] = Ahs[basea+c4];      ah[1] = Ahs[basea+160+c4];
                ah[2] = Ahs[basea+c4+4];    ah[3] = Ahs[basea+160+c4+4];
                al[0] = Als[basea+c4];      al[1] = Als[basea+160+c4];
                al[2] = Als[basea+c4+4];    al[3] = Als[basea+160+c4+4];
#pragma unroll
                for (int nt = 0; nt < 4; nt++) {
                    mma16(c[mt][nt], ah, bh[nt][0], bh[nt][1]);
                    mma16(c[mt][nt], ah, bl[nt][0], bl[nt][1]);
                    mma16(c[mt][nt], al, bh[nt][0], bh[nt][1]);
                }
            }
        }
    }

    // epilogue
    int c4 = lane&3, rg = lane>>2;
#pragma unroll
    for (int mt = 0; mt < 4; mt++) {
        int rbase = bm + wm + mt*16 + rg;
#pragma unroll
        for (int half = 0; half < 2; half++) {
            int row = rbase + half*8;
            int b_ = row / 196;
            int n  = row % 196;
#pragma unroll
            for (int nt = 0; nt < 4; nt++) {
#pragma unroll
                for (int e = 0; e < 2; e++) {
                    int col = bn + wn + nt*8 + c4*2 + e;
                    float v = c[mt][nt][half*2+e] + bias[col];
                    if (EPI == 0) {
                        int kvsel = col >> 9;
                        int hh = (col>>5)&15, d = col&31;
                        uint32_t* dst = kvsel ? g_v : g_k;
                        dst[(((size_t)b_*16+hh)*196+n)*32+d] = cvt_tf32(v);
                    } else {
                        out[(size_t)row*512 + col] = v;
                    }
                }
            }
        }
    }
}

// ---------------- fused attention: one block per (b_, h), 13 warps ----------------
__global__ void __launch_bounds__(416,1) attn_kernel(const float* __restrict__ qg){
    extern __shared__ uint32_t smu[];
    uint32_t* Ks = smu;                       // 7200 words
    uint32_t* Vs = smu + 7200;                // 7200 words
    float* Ps = (float*)(smu + 14400);        // 13*16*204 = 42432
    float* Rs = Ps + 42432;                   // 208

    int h = blockIdx.x, b_ = blockIdx.y, b = b_ >> 6;
    int tid = threadIdx.x, lane = tid&31, wid = tid>>5;

    const uint4* kg = (const uint4*)(g_k + (((size_t)b_*16 + h)*196)*32);
    const uint4* vg = (const uint4*)(g_v + (((size_t)b_*16 + h)*196)*32);

    for (int i = tid; i < 1600; i += 416) {
        int r = i>>3, q = (i&7)*4;
        uint4 zk = make_uint4(0,0,0,0);
        uint4 zv = make_uint4(0,0,0,0);
        if (r < 196) {
            zk = kg[r*8 + (i&7)];
            zv = vg[r*8 + (i&7)];
        }
        *(uint4*)(Ks + r*36 + q) = zk;
        *(uint4*)(Vs + r*36 + q) = zv;
    }
    __syncthreads();

    const float* bptr  = g_bias + (size_t)h*NTOK*NTOK;
    const float* qbase = qg + (((size_t)b*16 + h)*196)*32;
    const float scale = 0.17677669529663687f;
    float* Pw = Ps + wid*16*204;

    {
        int t = wid;
        int r0 = t*16 + (lane>>2), r1 = r0 + 8;

        uint32_t qhi[4][4], qlo[4][4];
#pragma unroll
        for (int kt = 0; kt < 4; kt++) {
            int k = kt*8 + (lane&3);
            float x0 = (r0 < 196) ? qbase[r0*32+k]*scale   : 0.f;
            float x1 = (r1 < 196) ? qbase[r1*32+k]*scale   : 0.f;
            float x2 = (r0 < 196) ? qbase[r0*32+k+4]*scale : 0.f;
            float x3 = (r1 < 196) ? qbase[r1*32+k+4]*scale : 0.f;
            split2(x0, qhi[kt][0], qlo[kt][0]);
            split2(x1, qhi[kt][1], qlo[kt][1]);
            split2(x2, qhi[kt][2], qlo[kt][2]);
            split2(x3, qhi[kt][3], qlo[kt][3]);
        }

        for (int nt = 0; nt < 25; nt++) {
            int cc = nt*8 + (lane&3)*2;
            float bv0 = 0.f, bv1 = 0.f, bv2 = 0.f, bv3 = 0.f;
            bool cok0 = cc < 196, cok1 = (cc+1) < 196;
            if (cok0 && r0 < 196) bv0 = bptr[r0*196+cc];
            if (cok1 && r0 < 196) bv1 = bptr[r0*196+cc+1];
            if (cok0 && r1 < 196) bv2 = bptr[r1*196+cc];
            if (cok1 && r1 < 196) bv3 = bptr[r1*196+cc+1];

            float cfr[4] = {0.f,0.f,0.f,0.f};
#pragma unroll
            for (int kt = 0; kt < 4; kt++) {
                int k = kt*8 + (lane&3);
                int cb = nt*8 + (lane>>2);
                uint32_t b0 = Ks[cb*36+k];
                uint32_t b1 = Ks[cb*36+k+4];
                mma8(cfr, qhi[kt], b0, b1);
                mma8(cfr, qlo[kt], b0, b1);
            }
            int rr = lane>>2;
            Pw[rr*204+cc]       = cok0 ? cfr[0]+bv0 : -1e30f;
            Pw[rr*204+cc+1]     = cok1 ? cfr[1]+bv1 : -1e30f;
            Pw[(rr+8)*204+cc]   = cok0 ? cfr[2]+bv2 : -1e30f;
            Pw[(rr+8)*204+cc+1] = cok1 ? cfr[3]+bv3 : -1e30f;
        }
        __syncwarp();

        {
            int rr = lane>>1, hf = lane&1;
            float* pr = Pw + rr*204 + hf*100;
            float mx = -1e30f;
            for (int j = 0; j < 100; j++) mx = fmaxf(mx, pr[j]);
            mx = fmaxf(mx, __shfl_xor_sync(0xffffffffu, mx, 1));
            float sum = 0.f;
            for (int j = 0; j < 100; j++) {
                float e = __expf(pr[j] - mx);
                pr[j] = e;
                sum += e;
            }
            sum += __shfl_xor_sync(0xffffffffu, sum, 1);
            if (hf == 0) Rs[wid*16+rr] = 1.f/sum;
        }
        __syncwarp();

        float o[4][4] = {};
        for (int kt = 0; kt < 25; kt++) {
            int k = kt*8 + (lane&3);
            int g = lane>>2;
            uint32_t phi[4], plo[4];
            split2(Pw[g*204+k],       phi[0], plo[0]);
            split2(Pw[(g+8)*204+k],   phi[1], plo[1]);
            split2(Pw[g*204+k+4],     phi[2], plo[2]);
            split2(Pw[(g+8)*204+k+4], phi[3], plo[3]);
#pragma unroll
            for (int dt = 0; dt < 4; dt++) {
                int d = dt*8 + g;
                uint32_t b0 = Vs[k*36+d];
                uint32_t b1 = Vs[(k+4)*36+d];
                mma8(o[dt], phi, b0, b1);
                mma8(o[dt], plo, b0, b1);
            }
        }

        // epilogue: fold 1/rowsum, write bf16 hi/lo pairs into row-major planes
        float inv0 = Rs[wid*16 + (lane>>2)];
        float inv1 = Rs[wid*16 + (lane>>2) + 8];
#pragma unroll
        for (int dt = 0; dt < 4; dt++) {
            int d2 = dt*8 + (lane&3)*2;
            int col = h*32 + d2;
            if (r0 < 196) {
                uint16_t h0,l0,h1,l1;
                bsplit(o[dt][0]*inv0, h0, l0);
                bsplit(o[dt][1]*inv0, h1, l1);
                size_t e = ((size_t)(b_*196 + r0)*512 + col) >> 1;
                ((uint32_t*)g_ahi)[e] = (uint32_t)h0 | ((uint32_t)h1<<16);
                ((uint32_t*)g_alo)[e] = (uint32_t)l0 | ((uint32_t)l1<<16);
            }
            if (r1 < 196) {
                uint16_t h0,l0,h1,l1;
                bsplit(o[dt][2]*inv1, h0, l0);
                bsplit(o[dt][3]*inv1, h1, l1);
                size_t e = ((size_t)(b_*196 + r1)*512 + col) >> 1;
                ((uint32_t*)g_ahi)[e] = (uint32_t)h0 | ((uint32_t)h1<<16);
                ((uint32_t*)g_alo)[e] = (uint32_t)l0 | ((uint32_t)l1<<16);
            }
        }
    }
}

extern "C" void kernel_launch(void* const* d_in, const int* in_sizes, int n_in,
                              void* d_out, int out_size) {
    const float* x   = (const float*)d_in[0];
    const float* qg  = (const float*)d_in[1];
    const float* kvw = (const float*)d_in[2];
    const float* kvb = (const float*)d_in[3];
    const float* pw  = (const float*)d_in[4];
    const float* pb  = (const float*)d_in[5];
    const float* bt  = (const float*)d_in[6];
    float* out = (float*)d_out;

    split_x_kernel<<<4096, 256>>>(x);
    conv_w_kernel<<<384, 256>>>(kvw, pw);
    bias_gather_kernel<<<2402, 256>>>(bt);

    const int GSMEM = 81920;
    cudaFuncSetAttribute(gemm_kernel<0>, cudaFuncAttributeMaxDynamicSharedMemorySize, GSMEM);
    cudaFuncSetAttribute(gemm_kernel<1>, cudaFuncAttributeMaxDynamicSharedMemorySize, GSMEM);

    gemm_kernel<0><<<dim3(8,392), 256, GSMEM>>>(kvb, nullptr);

    cudaFuncSetAttribute(attn_kernel, cudaFuncAttributeMaxDynamicSharedMemorySize, 228160);
    attn_kernel<<<dim3(16,256), 416, 228160>>>(qg);

    gemm_kernel<1><<<dim3(4,392), 256, GSMEM>>>(pb, out);
}